// round 6
// baseline (speedup 1.0000x reference)
#include <cuda_runtime.h>
#include <cuda_fp16.h>
#include <math.h>
#include <stdint.h>

#define BATCH 16
#define SEQ   4096
#define DIM   1280
#define TOK   77
#define CDIM  768
#define HEADS 8
#define DHEAD 160
#define JDIM  616
#define JPAD  640
#define ROWS_KV 1232            /* BATCH*TOK */
#define ROWS_KV_PAD 1280

// ---------------------------------------------------------------------------
// Scratch (static device globals)
// ---------------------------------------------------------------------------
__device__ __align__(256) float g_K [ROWS_KV_PAD*DIM];
__device__ __align__(256) float g_V [ROWS_KV_PAD*DIM];
__device__ __align__(256) float g_S [(size_t)BATCH*SEQ*JPAD];       // scores fp32
__device__ __align__(256) __half g_Xf [(size_t)BATCH*SEQ*DIM];      // X fp16
__device__ __align__(256) __half g_Ef [(size_t)ROWS_KV_PAD*CDIM];   // E fp16 (padded rows)
__device__ __align__(256) __half g_wkf[(size_t)DIM*CDIM];           // wk fp16
__device__ __align__(256) __half g_wvf[(size_t)DIM*CDIM];           // wv fp16
__device__ __align__(256) __half g_A [(size_t)BATCH*JPAD*DIM];      // AfoldT fp16
__device__ __align__(256) __half g_B2[(size_t)BATCH*DIM*JPAD];      // B2T fp16
__device__ __align__(256) __half g_P [(size_t)BATCH*SEQ*JPAD];      // probs fp16

// ---------------------------------------------------------------------------
// helpers
// ---------------------------------------------------------------------------
__device__ __forceinline__ uint32_t smem_u32(const void* p) {
    uint32_t a;
    asm("{ .reg .u64 t; cvta.to.shared.u64 t, %1; cvt.u32.u64 %0, t; }"
        : "=r"(a) : "l"(p));
    return a;
}

#define SWZ128(o) ((o) ^ (((o) >> 3) & 0x70))

__device__ __forceinline__ void cp16(uint32_t s, const void* g) {
    asm volatile("cp.async.cg.shared.global [%0], [%1], 16;" :: "r"(s), "l"(g));
}
#define CP_COMMIT() asm volatile("cp.async.commit_group;" ::: "memory")

__device__ __forceinline__ void ldsm4(uint32_t& r0, uint32_t& r1,
                                      uint32_t& r2, uint32_t& r3, uint32_t addr) {
    asm volatile("ldmatrix.sync.aligned.m8n8.x4.shared.b16 {%0,%1,%2,%3}, [%4];"
                 : "=r"(r0), "=r"(r1), "=r"(r2), "=r"(r3) : "r"(addr));
}

__device__ __forceinline__ void mma16816(float* c, uint32_t a0, uint32_t a1,
                                         uint32_t a2, uint32_t a3,
                                         uint32_t b0, uint32_t b1) {
    asm volatile(
        "mma.sync.aligned.m16n8k16.row.col.f32.f16.f16.f32 "
        "{%0,%1,%2,%3}, {%4,%5,%6,%7}, {%8,%9}, {%0,%1,%2,%3};"
        : "+f"(c[0]), "+f"(c[1]), "+f"(c[2]), "+f"(c[3])
        : "r"(a0), "r"(a1), "r"(a2), "r"(a3), "r"(b0), "r"(b1));
}

// ---------------------------------------------------------------------------
// warp-MMA GEMM:  C[m][n] = sum_k A[m][k]*B[n][k]   (single-pass fp16)
// CTA tile 128x128, 8 warps (4M x 2N), warp tile 32x64.
// KC=64; stage = 2 tiles (32 KB); 3 stages = 96 KB; 2 CTAs/SM.
// ---------------------------------------------------------------------------
#define KC 64
#define TILE_B 16384
#define STAGE_B (2*TILE_B)
#define NSTAGE 3
#define MM_SMEM (NSTAGE*STAGE_B)

__global__ __launch_bounds__(256, 2)
void mma_gemm(const __half* __restrict__ A, const __half* __restrict__ B,
              float* __restrict__ C, const float* __restrict__ bias,
              int K, int ldc, long sA, long sB, long sC)
{
    extern __shared__ __align__(1024) char smem[];
    const uint32_t sbase = smem_u32(smem);
    const int tid  = threadIdx.x;
    const int wid  = tid >> 5;
    const int lane = tid & 31;
    const int wm   = wid & 3;
    const int wn   = wid >> 2;

    const char* baseA = (const char*)(A + (long)blockIdx.z * sA
                                        + (long)(blockIdx.y * 128) * K);
    const char* baseB = (const char*)(B + (long)blockIdx.z * sB
                                        + (long)(blockIdx.x * 128) * K);

    uint32_t soff[4], goff[4];
    #pragma unroll
    for (int i = 0; i < 4; ++i) {
        int idx = tid + i * 256;
        int r = (idx >> 3) & 127;
        int u = idx & 7;
        soff[i] = SWZ128((uint32_t)(r * 128 + u * 16));
        goff[i] = (uint32_t)(r * (K * 2) + u * 16);
    }

    uint32_t aRowOff[2], aXor[2];
    #pragma unroll
    for (int mi = 0; mi < 2; ++mi) {
        int r = wm * 32 + mi * 16 + (lane & 15);
        aRowOff[mi] = (uint32_t)(r * 128);
        aXor[mi]    = (uint32_t)((r & 7) * 16);
    }
    const uint32_t aG = (uint32_t)((lane >> 4) * 16);

    uint32_t bRowOff[4], bXor[4];
    #pragma unroll
    for (int q = 0; q < 4; ++q) {
        int r = wn * 64 + q * 16 + (lane & 7) + ((lane >> 4) << 3);
        bRowOff[q] = (uint32_t)(r * 128);
        bXor[q]    = (uint32_t)((r & 7) * 16);
    }
    const uint32_t bG = (uint32_t)(((lane >> 3) & 1) * 16);

    float acc[2][8][4];
    #pragma unroll
    for (int mi = 0; mi < 2; ++mi)
        #pragma unroll
        for (int ni = 0; ni < 8; ++ni)
            #pragma unroll
            for (int e = 0; e < 4; ++e) acc[mi][ni][e] = 0.f;

    const int nk = K / KC;

    #pragma unroll
    for (int i = 0; i < 4; ++i) {
        cp16(sbase + soff[i],          baseA + goff[i]);
        cp16(sbase + TILE_B + soff[i], baseB + goff[i]);
    }
    CP_COMMIT();
    #pragma unroll
    for (int i = 0; i < 4; ++i) {
        cp16(sbase + STAGE_B + soff[i],          baseA + goff[i] + 128);
        cp16(sbase + STAGE_B + TILE_B + soff[i], baseB + goff[i] + 128);
    }
    CP_COMMIT();
    #pragma unroll
    for (int i = 0; i < 4; ++i) goff[i] += 256;

    for (int k = 0; k < nk; ++k) {
        if (k + 2 < nk) {
            const uint32_t sb = sbase + ((k + 2) % NSTAGE) * STAGE_B;
            #pragma unroll
            for (int i = 0; i < 4; ++i) {
                cp16(sb + soff[i],          baseA + goff[i]);
                cp16(sb + TILE_B + soff[i], baseB + goff[i]);
            }
            CP_COMMIT();
            #pragma unroll
            for (int i = 0; i < 4; ++i) goff[i] += 128;
            asm volatile("cp.async.wait_group 2;" ::: "memory");
        } else if (k + 1 < nk) {
            asm volatile("cp.async.wait_group 1;" ::: "memory");
        } else {
            asm volatile("cp.async.wait_group 0;" ::: "memory");
        }
        __syncthreads();

        const uint32_t aT = sbase + (k % NSTAGE) * STAGE_B;
        const uint32_t bT = aT + TILE_B;
        #pragma unroll
        for (int kk = 0; kk < 4; ++kk) {
            const uint32_t kb = (uint32_t)(kk * 32);
            uint32_t a[2][4];
            #pragma unroll
            for (int mi = 0; mi < 2; ++mi)
                ldsm4(a[mi][0], a[mi][1], a[mi][2], a[mi][3],
                      aT + aRowOff[mi] + ((aG + kb) ^ aXor[mi]));
            uint32_t b[4][4];
            #pragma unroll
            for (int q = 0; q < 4; ++q)
                ldsm4(b[q][0], b[q][1], b[q][2], b[q][3],
                      bT + bRowOff[q] + ((bG + kb) ^ bXor[q]));
            #pragma unroll
            for (int mi = 0; mi < 2; ++mi)
                #pragma unroll
                for (int q = 0; q < 4; ++q) {
                    mma16816(acc[mi][q * 2 + 0],
                             a[mi][0], a[mi][1], a[mi][2], a[mi][3],
                             b[q][0], b[q][1]);
                    mma16816(acc[mi][q * 2 + 1],
                             a[mi][0], a[mi][1], a[mi][2], a[mi][3],
                             b[q][2], b[q][3]);
                }
        }
        __syncthreads();
    }

    const int row0 = blockIdx.y * 128 + wm * 32 + (lane >> 2);
    const int col0 = blockIdx.x * 128 + wn * 64 + (lane & 3) * 2;
    float* Cb = C + (long)blockIdx.z * sC;
    #pragma unroll
    for (int mi = 0; mi < 2; ++mi) {
        #pragma unroll
        for (int ni = 0; ni < 8; ++ni) {
            const int r = row0 + mi * 16;
            const int c = col0 + ni * 8;
            float bx = 0.f, by = 0.f;
            if (bias) { bx = bias[c]; by = bias[c + 1]; }
            float2 v0 = make_float2(acc[mi][ni][0] + bx, acc[mi][ni][1] + by);
            float2 v1 = make_float2(acc[mi][ni][2] + bx, acc[mi][ni][3] + by);
            *reinterpret_cast<float2*>(Cb + (long)r * ldc + c)       = v0;
            *reinterpret_cast<float2*>(Cb + (long)(r + 8) * ldc + c) = v1;
        }
    }
}

// ---------------------------------------------------------------------------
// fold_A: AfoldT[b][h*77+t][c] (fp16) = d^-0.5 * sum_e wq[h*160+e][c]*K[b,t][h*160+e]
// 320 threads: 16 c-groups (8 c, float4 x2) x 20 t-groups (4 t, float4).
// ---------------------------------------------------------------------------
__global__ __launch_bounds__(320) void fold_A(
    const float* __restrict__ wq, const float* __restrict__ Kmat,
    __half* __restrict__ outH)
{
    const int b = blockIdx.z, hd = blockIdx.y;
    const int c0 = blockIdx.x * 128;
    __shared__ float Ws[16][128];   // [e][c]
    __shared__ float Ks[16][84];    // [e][t], padded

    const int tid  = threadIdx.x;
    const int tcid = tid & 15;      // c group
    const int ttid = tid >> 4;      // t group 0..19
    const float scale = 0.07905694150420949f;

    float acc[8][4];
    #pragma unroll
    for (int i = 0; i < 8; i++)
        #pragma unroll
        for (int j = 0; j < 4; j++) acc[i][j] = 0.f;

    for (int e0 = 0; e0 < DHEAD; e0 += 16) {
        for (int idx = tid; idx < 512; idx += 320) {
            const int k = idx >> 5, c4 = idx & 31;
            float4 v = *reinterpret_cast<const float4*>(
                wq + (long)(hd * DHEAD + e0 + k) * DIM + c0 + c4 * 4);
            *reinterpret_cast<float4*>(&Ws[k][c4 * 4]) = v;
        }
        for (int idx = tid; idx < 1280; idx += 320) {
            const int t = idx >> 4, k = idx & 15;
            Ks[k][t] = (t < TOK)
                ? Kmat[(long)(b * TOK + t) * DIM + hd * DHEAD + e0 + k] : 0.f;
        }
        __syncthreads();
        #pragma unroll
        for (int k = 0; k < 16; k++) {
            float4 w0 = *reinterpret_cast<const float4*>(&Ws[k][tcid * 8]);
            float4 w1 = *reinterpret_cast<const float4*>(&Ws[k][tcid * 8 + 4]);
            float4 kv = *reinterpret_cast<const float4*>(&Ks[k][ttid * 4]);
            const float wv[8] = {w0.x, w0.y, w0.z, w0.w, w1.x, w1.y, w1.z, w1.w};
            const float tv[4] = {kv.x, kv.y, kv.z, kv.w};
            #pragma unroll
            for (int i = 0; i < 8; i++)
                #pragma unroll
                for (int j = 0; j < 4; j++)
                    acc[i][j] = fmaf(wv[i], tv[j], acc[i][j]);
        }
        __syncthreads();
    }
    #pragma unroll
    for (int j = 0; j < 4; j++) {
        const int t = ttid * 4 + j;
        if (t >= TOK) continue;
        __half2 p0 = __floats2half2_rn(acc[0][j] * scale, acc[1][j] * scale);
        __half2 p1 = __floats2half2_rn(acc[2][j] * scale, acc[3][j] * scale);
        __half2 p2 = __floats2half2_rn(acc[4][j] * scale, acc[5][j] * scale);
        __half2 p3 = __floats2half2_rn(acc[6][j] * scale, acc[7][j] * scale);
        uint4 u;
        u.x = *reinterpret_cast<uint32_t*>(&p0);
        u.y = *reinterpret_cast<uint32_t*>(&p1);
        u.z = *reinterpret_cast<uint32_t*>(&p2);
        u.w = *reinterpret_cast<uint32_t*>(&p3);
        *reinterpret_cast<uint4*>(
            outH + ((long)b * JPAD + hd * TOK + t) * DIM + c0 + tcid * 8) = u;
    }
}

// ---------------------------------------------------------------------------
// fold_B: B2T[b][e2][h*77+t] (fp16) = sum_e V[b,t][h*160+e]*wout[e2][h*160+e]
// ---------------------------------------------------------------------------
__global__ __launch_bounds__(320) void fold_B(
    const float* __restrict__ wout, const float* __restrict__ Vmat,
    __half* __restrict__ outH)
{
    const int b = blockIdx.z, hd = blockIdx.y;
    const int n0 = blockIdx.x * 128;
    __shared__ float Ws[16][132];   // [e][n], padded (132 % 4 == 0)
    __shared__ float Vs[16][84];    // [e][t], padded

    const int tid  = threadIdx.x;
    const int tcid = tid & 15;      // n group (8)
    const int ttid = tid >> 4;      // t group (4)

    float acc[4][8];
    #pragma unroll
    for (int j = 0; j < 4; j++)
        #pragma unroll
        for (int i = 0; i < 8; i++) acc[j][i] = 0.f;

    for (int e0 = 0; e0 < DHEAD; e0 += 16) {
        for (int idx = tid; idx < 2048; idx += 320) {
            const int n = idx >> 4, k = idx & 15;
            Ws[k][n] = wout[(long)(n0 + n) * DIM + hd * DHEAD + e0 + k];
        }
        for (int idx = tid; idx < 1280; idx += 320) {
            const int t = idx >> 4, k = idx & 15;
            Vs[k][t] = (t < TOK)
                ? Vmat[(long)(b * TOK + t) * DIM + hd * DHEAD + e0 + k] : 0.f;
        }
        __syncthreads();
        #pragma unroll
        for (int k = 0; k < 16; k++) {
            float4 w0 = *reinterpret_cast<const float4*>(&Ws[k][tcid * 8]);
            float4 w1 = *reinterpret_cast<const float4*>(&Ws[k][tcid * 8 + 4]);
            float4 vv = *reinterpret_cast<const float4*>(&Vs[k][ttid * 4]);
            const float wv[8] = {w0.x, w0.y, w0.z, w0.w, w1.x, w1.y, w1.z, w1.w};
            const float tv[4] = {vv.x, vv.y, vv.z, vv.w};
            #pragma unroll
            for (int j = 0; j < 4; j++)
                #pragma unroll
                for (int i = 0; i < 8; i++)
                    acc[j][i] = fmaf(tv[j], wv[i], acc[j][i]);
        }
        __syncthreads();
    }
    #pragma unroll
    for (int j = 0; j < 4; j++) {
        const int t = ttid * 4 + j;
        if (t >= TOK) continue;
        #pragma unroll
        for (int i = 0; i < 8; i++) {
            const int n = n0 + tcid * 8 + i;
            outH[((long)b * DIM + n) * JPAD + hd * TOK + t] =
                __float2half_rn(acc[j][i]);
        }
    }
}

// ---------------------------------------------------------------------------
// zero pads (AfoldT rows 616..639; B2T cols 616..639)
// ---------------------------------------------------------------------------
__global__ void zero_pads(__half* A, __half* B2)
{
    const int PAD = JPAD - JDIM;               // 24
    const int n1 = BATCH * PAD * DIM;
    const int n2 = BATCH * DIM * PAD;
    const __half z = __float2half_rn(0.f);
    for (int i = blockIdx.x * blockDim.x + threadIdx.x; i < n1 + n2;
         i += gridDim.x * blockDim.x) {
        if (i < n1) {
            int b = i / (PAD * DIM);
            int rem = i % (PAD * DIM);
            int r = rem / DIM, c = rem % DIM;
            A[((long)b * JPAD + JDIM + r) * DIM + c] = z;
        } else {
            int j = i - n1;
            int b = j / (DIM * PAD);
            int rem = j % (DIM * PAD);
            int e = rem / PAD, t = rem % PAD;
            B2[((long)b * DIM + e) * JPAD + JDIM + t] = z;
        }
    }
}

// ---------------------------------------------------------------------------
// fp32 -> fp16 convert
// ---------------------------------------------------------------------------
__global__ void cvt_h4(const float4* __restrict__ src,
                       __half2* __restrict__ dst, long n4)
{
    for (long i = (long)blockIdx.x * blockDim.x + threadIdx.x; i < n4;
         i += (long)gridDim.x * blockDim.x) {
        float4 v = src[i];
        dst[2 * i]     = __floats2half2_rn(v.x, v.y);
        dst[2 * i + 1] = __floats2half2_rn(v.z, v.w);
    }
}

// ---------------------------------------------------------------------------
// fused softmax(77-group) -> fp16 probs; zeros prob pad cols
// ---------------------------------------------------------------------------
__global__ __launch_bounds__(256) void softmax77h(const float* __restrict__ Smat,
                                                  __half* __restrict__ P)
{
    const int gw   = blockIdx.x * 8 + (threadIdx.x >> 5);
    const int lane = threadIdx.x & 31;
    const int row  = gw >> 3;
    const int h    = gw & 7;
    const long base = (long)row * JPAD + h * TOK;

    const float NEG = -1e30f;
    float x0 = Smat[base + lane];
    float x1 = Smat[base + 32 + lane];
    float x2 = (lane < 13) ? Smat[base + 64 + lane] : NEG;

    float m = fmaxf(x0, fmaxf(x1, x2));
    #pragma unroll
    for (int o = 16; o > 0; o >>= 1)
        m = fmaxf(m, __shfl_xor_sync(0xffffffffu, m, o));

    float e0 = expf(x0 - m);
    float e1 = expf(x1 - m);
    float e2 = (lane < 13) ? expf(x2 - m) : 0.f;
    float s = e0 + e1 + e2;
    #pragma unroll
    for (int o = 16; o > 0; o >>= 1)
        s += __shfl_xor_sync(0xffffffffu, s, o);

    const float inv = 1.f / s;
    P[base + lane]      = __float2half_rn(e0 * inv);
    P[base + 32 + lane] = __float2half_rn(e1 * inv);
    if (lane < 13) P[base + 64 + lane] = __float2half_rn(e2 * inv);
    if (h == 7 && lane < JPAD - JDIM)
        P[(long)row * JPAD + JDIM + lane] = __float2half_rn(0.f);
}

// ---------------------------------------------------------------------------
extern "C" void kernel_launch(void* const* d_in, const int* in_sizes, int n_in,
                              void* d_out, int out_size)
{
    const float* X  = (const float*)d_in[0];
    const float* E  = (const float*)d_in[1];
    const float* wq = (const float*)d_in[2];
    const float* wk = (const float*)d_in[3];
    const float* wv = (const float*)d_in[4];
    const float* wo = (const float*)d_in[5];
    const float* bo = (const float*)d_in[6];
    float* out = (float*)d_out;

    float *pK, *pV, *pS;
    __half *pXf, *pEf, *pWkf, *pWvf, *pA, *pB2, *pP;
    cudaGetSymbolAddress((void**)&pK,   g_K);
    cudaGetSymbolAddress((void**)&pV,   g_V);
    cudaGetSymbolAddress((void**)&pS,   g_S);
    cudaGetSymbolAddress((void**)&pXf,  g_Xf);
    cudaGetSymbolAddress((void**)&pEf,  g_Ef);
    cudaGetSymbolAddress((void**)&pWkf, g_wkf);
    cudaGetSymbolAddress((void**)&pWvf, g_wvf);
    cudaGetSymbolAddress((void**)&pA,   g_A);
    cudaGetSymbolAddress((void**)&pB2,  g_B2);
    cudaGetSymbolAddress((void**)&pP,   g_P);

    cudaFuncSetAttribute(mma_gemm, cudaFuncAttributeMaxDynamicSharedMemorySize,
                         MM_SMEM);

    // fp32 -> fp16 conversions (E, wk, wv, X)
    cvt_h4<<<1024, 256>>>((const float4*)E, (__half2*)pEf,
                          (long)ROWS_KV * CDIM / 4);
    cvt_h4<<<1024, 256>>>((const float4*)wk, (__half2*)pWkf,
                          (long)DIM * CDIM / 4);
    cvt_h4<<<1024, 256>>>((const float4*)wv, (__half2*)pWvf,
                          (long)DIM * CDIM / 4);
    cvt_h4<<<8192, 256>>>((const float4*)X, (__half2*)pXf,
                          (long)BATCH * SEQ * DIM / 4);

    // K/V projections via MMA: K[r][d] = E[r]·wk[d]  (rows padded to 1280)
    mma_gemm<<<dim3(DIM / 128, ROWS_KV_PAD / 128, 1), 256, MM_SMEM>>>(
        pEf, pWkf, pK, nullptr, CDIM, DIM, 0, 0, 0);
    mma_gemm<<<dim3(DIM / 128, ROWS_KV_PAD / 128, 1), 256, MM_SMEM>>>(
        pEf, pWvf, pV, nullptr, CDIM, DIM, 0, 0, 0);

    // folded operand matrices (fp16, K-major)
    fold_A<<<dim3(10, 8, 16), 320>>>(wq, pK, pA);
    fold_B<<<dim3(10, 8, 16), 320>>>(wo, pV, pB2);
    zero_pads<<<2048, 256>>>(pA, pB2);

    // scores: S[b][s][j] = sum_c X[s][c] * AfoldT[j][c]
    mma_gemm<<<dim3(JPAD / 128, SEQ / 128, BATCH), 256, MM_SMEM>>>(
        pXf, pA, pS, nullptr, DIM, JPAD,
        (long)SEQ * DIM, (long)JPAD * DIM, (long)SEQ * JPAD);

    // fused softmax -> fp16 probs
    softmax77h<<<BATCH * SEQ, 256>>>(pS, pP);

    // output: out[b][s][e] = sum_j P[s][j] * B2T[e][j] + bias[e]
    mma_gemm<<<dim3(DIM / 128, SEQ / 128, BATCH), 256, MM_SMEM>>>(
        pP, pB2, out, bo, JPAD, DIM,
        (long)SEQ * JPAD, (long)DIM * JPAD, (long)SEQ * DIM);
}

// round 7
// speedup vs baseline: 1.4765x; 1.4765x over previous
#include <cuda_runtime.h>
#include <cuda_fp16.h>
#include <math.h>
#include <stdint.h>

#define BATCH 16
#define SEQ   4096
#define DIM   1280
#define TOK   77
#define CDIM  768
#define HEADS 8
#define DHEAD 160
#define JDIM  616
#define JPAD  640
#define ROWS_KV 1232            /* BATCH*TOK */
#define ROWS_KV_PAD 1280

// ---------------------------------------------------------------------------
// Scratch (static device globals)
// ---------------------------------------------------------------------------
__device__ __align__(256) float g_K [ROWS_KV_PAD*DIM];
__device__ __align__(256) float g_V [ROWS_KV_PAD*DIM];
__device__ __align__(256) float g_S [(size_t)BATCH*SEQ*JPAD];       // scores fp32
__device__ __align__(256) __half g_Xf [(size_t)BATCH*SEQ*DIM];      // X fp16
__device__ __align__(256) __half g_Ef [(size_t)ROWS_KV_PAD*CDIM];   // E fp16 (padded rows)
__device__ __align__(256) __half g_wkf[(size_t)DIM*CDIM];           // wk fp16
__device__ __align__(256) __half g_wvf[(size_t)DIM*CDIM];           // wv fp16
__device__ __align__(256) __half g_A [(size_t)BATCH*JPAD*DIM];      // AfoldT fp16
__device__ __align__(256) __half g_B2[(size_t)BATCH*DIM*JPAD];      // B2T fp16
__device__ __align__(256) __half g_P [(size_t)BATCH*SEQ*JPAD];      // probs fp16

// ---------------------------------------------------------------------------
// helpers
// ---------------------------------------------------------------------------
__device__ __forceinline__ uint32_t smem_u32(const void* p) {
    uint32_t a;
    asm("{ .reg .u64 t; cvta.to.shared.u64 t, %1; cvt.u32.u64 %0, t; }"
        : "=r"(a) : "l"(p));
    return a;
}

#define SWZ128(o) ((o) ^ (((o) >> 3) & 0x70))

__device__ __forceinline__ void cp16(uint32_t s, const void* g) {
    asm volatile("cp.async.cg.shared.global [%0], [%1], 16;" :: "r"(s), "l"(g));
}
#define CP_COMMIT() asm volatile("cp.async.commit_group;" ::: "memory")

__device__ __forceinline__ void ldsm4(uint32_t& r0, uint32_t& r1,
                                      uint32_t& r2, uint32_t& r3, uint32_t addr) {
    asm volatile("ldmatrix.sync.aligned.m8n8.x4.shared.b16 {%0,%1,%2,%3}, [%4];"
                 : "=r"(r0), "=r"(r1), "=r"(r2), "=r"(r3) : "r"(addr));
}

__device__ __forceinline__ void mma16816(float* c, uint32_t a0, uint32_t a1,
                                         uint32_t a2, uint32_t a3,
                                         uint32_t b0, uint32_t b1) {
    asm volatile(
        "mma.sync.aligned.m16n8k16.row.col.f32.f16.f16.f32 "
        "{%0,%1,%2,%3}, {%4,%5,%6,%7}, {%8,%9}, {%0,%1,%2,%3};"
        : "+f"(c[0]), "+f"(c[1]), "+f"(c[2]), "+f"(c[3])
        : "r"(a0), "r"(a1), "r"(a2), "r"(a3), "r"(b0), "r"(b1));
}

// ---------------------------------------------------------------------------
// warp-MMA GEMM:  C[m][n] = sum_k A[m][k]*B[n][k]   (single-pass fp16)
// CTA tile 128x128, 8 warps (4M x 2N), warp tile 32x64.
// KC=64; stage = 2 tiles (32 KB); 3 stages = 96 KB; 2 CTAs/SM.
// ---------------------------------------------------------------------------
#define KC 64
#define TILE_B 16384
#define STAGE_B (2*TILE_B)
#define NSTAGE 3
#define MM_SMEM (NSTAGE*STAGE_B)

__global__ __launch_bounds__(256, 2)
void mma_gemm(const __half* __restrict__ A, const __half* __restrict__ B,
              float* __restrict__ C, const float* __restrict__ bias,
              int K, int ldc, long sA, long sB, long sC)
{
    extern __shared__ __align__(1024) char smem[];
    const uint32_t sbase = smem_u32(smem);
    const int tid  = threadIdx.x;
    const int wid  = tid >> 5;
    const int lane = tid & 31;
    const int wm   = wid & 3;
    const int wn   = wid >> 2;

    const char* baseA = (const char*)(A + (long)blockIdx.z * sA
                                        + (long)(blockIdx.y * 128) * K);
    const char* baseB = (const char*)(B + (long)blockIdx.z * sB
                                        + (long)(blockIdx.x * 128) * K);

    uint32_t soff[4], goff[4];
    #pragma unroll
    for (int i = 0; i < 4; ++i) {
        int idx = tid + i * 256;
        int r = (idx >> 3) & 127;
        int u = idx & 7;
        soff[i] = SWZ128((uint32_t)(r * 128 + u * 16));
        goff[i] = (uint32_t)(r * (K * 2) + u * 16);
    }

    uint32_t aRowOff[2], aXor[2];
    #pragma unroll
    for (int mi = 0; mi < 2; ++mi) {
        int r = wm * 32 + mi * 16 + (lane & 15);
        aRowOff[mi] = (uint32_t)(r * 128);
        aXor[mi]    = (uint32_t)((r & 7) * 16);
    }
    const uint32_t aG = (uint32_t)((lane >> 4) * 16);

    uint32_t bRowOff[4], bXor[4];
    #pragma unroll
    for (int q = 0; q < 4; ++q) {
        int r = wn * 64 + q * 16 + (lane & 7) + ((lane >> 4) << 3);
        bRowOff[q] = (uint32_t)(r * 128);
        bXor[q]    = (uint32_t)((r & 7) * 16);
    }
    const uint32_t bG = (uint32_t)(((lane >> 3) & 1) * 16);

    float acc[2][8][4];
    #pragma unroll
    for (int mi = 0; mi < 2; ++mi)
        #pragma unroll
        for (int ni = 0; ni < 8; ++ni)
            #pragma unroll
            for (int e = 0; e < 4; ++e) acc[mi][ni][e] = 0.f;

    const int nk = K / KC;

    #pragma unroll
    for (int i = 0; i < 4; ++i) {
        cp16(sbase + soff[i],          baseA + goff[i]);
        cp16(sbase + TILE_B + soff[i], baseB + goff[i]);
    }
    CP_COMMIT();
    #pragma unroll
    for (int i = 0; i < 4; ++i) {
        cp16(sbase + STAGE_B + soff[i],          baseA + goff[i] + 128);
        cp16(sbase + STAGE_B + TILE_B + soff[i], baseB + goff[i] + 128);
    }
    CP_COMMIT();
    #pragma unroll
    for (int i = 0; i < 4; ++i) goff[i] += 256;

    for (int k = 0; k < nk; ++k) {
        if (k + 2 < nk) {
            const uint32_t sb = sbase + ((k + 2) % NSTAGE) * STAGE_B;
            #pragma unroll
            for (int i = 0; i < 4; ++i) {
                cp16(sb + soff[i],          baseA + goff[i]);
                cp16(sb + TILE_B + soff[i], baseB + goff[i]);
            }
            CP_COMMIT();
            #pragma unroll
            for (int i = 0; i < 4; ++i) goff[i] += 128;
            asm volatile("cp.async.wait_group 2;" ::: "memory");
        } else if (k + 1 < nk) {
            asm volatile("cp.async.wait_group 1;" ::: "memory");
        } else {
            asm volatile("cp.async.wait_group 0;" ::: "memory");
        }
        __syncthreads();

        const uint32_t aT = sbase + (k % NSTAGE) * STAGE_B;
        const uint32_t bT = aT + TILE_B;
        #pragma unroll
        for (int kk = 0; kk < 4; ++kk) {
            const uint32_t kb = (uint32_t)(kk * 32);
            uint32_t a[2][4];
            #pragma unroll
            for (int mi = 0; mi < 2; ++mi)
                ldsm4(a[mi][0], a[mi][1], a[mi][2], a[mi][3],
                      aT + aRowOff[mi] + ((aG + kb) ^ aXor[mi]));
            uint32_t b[4][4];
            #pragma unroll
            for (int q = 0; q < 4; ++q)
                ldsm4(b[q][0], b[q][1], b[q][2], b[q][3],
                      bT + bRowOff[q] + ((bG + kb) ^ bXor[q]));
            #pragma unroll
            for (int mi = 0; mi < 2; ++mi)
                #pragma unroll
                for (int q = 0; q < 4; ++q) {
                    mma16816(acc[mi][q * 2 + 0],
                             a[mi][0], a[mi][1], a[mi][2], a[mi][3],
                             b[q][0], b[q][1]);
                    mma16816(acc[mi][q * 2 + 1],
                             a[mi][0], a[mi][1], a[mi][2], a[mi][3],
                             b[q][2], b[q][3]);
                }
        }
        __syncthreads();
    }

    const int row0 = blockIdx.y * 128 + wm * 32 + (lane >> 2);
    const int col0 = blockIdx.x * 128 + wn * 64 + (lane & 3) * 2;
    float* Cb = C + (long)blockIdx.z * sC;
    #pragma unroll
    for (int mi = 0; mi < 2; ++mi) {
        #pragma unroll
        for (int ni = 0; ni < 8; ++ni) {
            const int r = row0 + mi * 16;
            const int c = col0 + ni * 8;
            float bx = 0.f, by = 0.f;
            if (bias) { bx = bias[c]; by = bias[c + 1]; }
            float2 v0 = make_float2(acc[mi][ni][0] + bx, acc[mi][ni][1] + by);
            float2 v1 = make_float2(acc[mi][ni][2] + bx, acc[mi][ni][3] + by);
            *reinterpret_cast<float2*>(Cb + (long)r * ldc + c)       = v0;
            *reinterpret_cast<float2*>(Cb + (long)(r + 8) * ldc + c) = v1;
        }
    }
}

// ---------------------------------------------------------------------------
// fold_A (round-5 proven version):
// AfoldT[b][h*77+t][c] (fp16) = d^-0.5 * sum_e wq[h*160+e][c]*K[b,t][h*160+e]
// ---------------------------------------------------------------------------
__global__ __launch_bounds__(256) void fold_A(
    const float* __restrict__ wq, const float* __restrict__ Kmat,
    __half* __restrict__ outH)
{
    const int b = blockIdx.z, hd = blockIdx.y;
    const int c0 = blockIdx.x * 128;
    __shared__ float Ws[16][128];
    __shared__ float Ks[16][80];

    const int tid  = threadIdx.x;
    const int tcid = tid & 15;
    const int ttid = tid >> 4;
    const float scale = 0.07905694150420949f;

    float acc[8][5];
    #pragma unroll
    for (int i = 0; i < 8; i++)
        #pragma unroll
        for (int j = 0; j < 5; j++) acc[i][j] = 0.f;

    for (int e0 = 0; e0 < DHEAD; e0 += 16) {
        {
            const int cc = (tid & 31) * 4;
            #pragma unroll
            for (int r = 0; r < 2; r++) {
                const int k = (tid >> 5) + r * 8;
                float4 v = *reinterpret_cast<const float4*>(
                    wq + (long)(hd * DHEAD + e0 + k) * DIM + c0 + cc);
                *reinterpret_cast<float4*>(&Ws[k][cc]) = v;
            }
        }
        for (int idx = tid; idx < TOK * 16; idx += 256) {
            const int t = idx >> 4, k = idx & 15;
            Ks[k][t] = Kmat[(long)(b * TOK + t) * DIM + hd * DHEAD + e0 + k];
        }
        for (int idx = tid; idx < 3 * 16; idx += 256)
            Ks[idx & 15][TOK + (idx >> 4)] = 0.f;
        __syncthreads();
        #pragma unroll
        for (int k = 0; k < 16; k++) {
            float w[8], kv[5];
            #pragma unroll
            for (int i = 0; i < 8; i++) w[i] = Ws[k][tcid * 8 + i];
            #pragma unroll
            for (int j = 0; j < 5; j++) kv[j] = Ks[k][ttid * 5 + j];
            #pragma unroll
            for (int i = 0; i < 8; i++)
                #pragma unroll
                for (int j = 0; j < 5; j++)
                    acc[i][j] = fmaf(w[i], kv[j], acc[i][j]);
        }
        __syncthreads();
    }
    #pragma unroll
    for (int i = 0; i < 8; i++) {
        const int c = c0 + tcid * 8 + i;
        #pragma unroll
        for (int j = 0; j < 5; j++) {
            const int t = ttid * 5 + j;
            if (t < TOK) {
                long off = ((long)b * JPAD + hd * TOK + t) * DIM + c;
                outH[off] = __float2half_rn(acc[i][j] * scale);
            }
        }
    }
}

// ---------------------------------------------------------------------------
// fold_B (round-5 proven version):
// B2T[b][e2][h*77+t] (fp16) = sum_e V[b,t][h*160+e]*wout[e2][h*160+e]
// ---------------------------------------------------------------------------
__global__ __launch_bounds__(256) void fold_B(
    const float* __restrict__ wout, const float* __restrict__ Vmat,
    __half* __restrict__ outH)
{
    const int b = blockIdx.z, hd = blockIdx.y;
    const int n0 = blockIdx.x * 128;
    __shared__ float Vs[16][80];
    __shared__ float Ws[16][128];

    const int tid  = threadIdx.x;
    const int tcid = tid & 15;
    const int ttid = tid >> 4;

    float acc[5][8];
    #pragma unroll
    for (int j = 0; j < 5; j++)
        #pragma unroll
        for (int i = 0; i < 8; i++) acc[j][i] = 0.f;

    for (int e0 = 0; e0 < DHEAD; e0 += 16) {
        for (int idx = tid; idx < 128 * 16; idx += 256) {
            const int n = idx >> 4, k = idx & 15;
            Ws[k][n] = wout[(long)(n0 + n) * DIM + hd * DHEAD + e0 + k];
        }
        for (int idx = tid; idx < TOK * 16; idx += 256) {
            const int t = idx >> 4, k = idx & 15;
            Vs[k][t] = Vmat[(long)(b * TOK + t) * DIM + hd * DHEAD + e0 + k];
        }
        for (int idx = tid; idx < 3 * 16; idx += 256)
            Vs[idx & 15][TOK + (idx >> 4)] = 0.f;
        __syncthreads();
        #pragma unroll
        for (int k = 0; k < 16; k++) {
            float vv[5], ww[8];
            #pragma unroll
            for (int j = 0; j < 5; j++) vv[j] = Vs[k][ttid * 5 + j];
            #pragma unroll
            for (int i = 0; i < 8; i++) ww[i] = Ws[k][tcid * 8 + i];
            #pragma unroll
            for (int j = 0; j < 5; j++)
                #pragma unroll
                for (int i = 0; i < 8; i++)
                    acc[j][i] = fmaf(vv[j], ww[i], acc[j][i]);
        }
        __syncthreads();
    }
    #pragma unroll
    for (int j = 0; j < 5; j++) {
        const int t = ttid * 5 + j;
        if (t >= TOK) continue;
        #pragma unroll
        for (int i = 0; i < 8; i++) {
            const int n = n0 + tcid * 8 + i;
            long off = ((long)b * DIM + n) * JPAD + hd * TOK + t;
            outH[off] = __float2half_rn(acc[j][i]);
        }
    }
}

// ---------------------------------------------------------------------------
// zero pads (AfoldT rows 616..639; B2T cols 616..639)
// ---------------------------------------------------------------------------
__global__ void zero_pads(__half* A, __half* B2)
{
    const int PAD = JPAD - JDIM;               // 24
    const int n1 = BATCH * PAD * DIM;
    const int n2 = BATCH * DIM * PAD;
    const __half z = __float2half_rn(0.f);
    for (int i = blockIdx.x * blockDim.x + threadIdx.x; i < n1 + n2;
         i += gridDim.x * blockDim.x) {
        if (i < n1) {
            int b = i / (PAD * DIM);
            int rem = i % (PAD * DIM);
            int r = rem / DIM, c = rem % DIM;
            A[((long)b * JPAD + JDIM + r) * DIM + c] = z;
        } else {
            int j = i - n1;
            int b = j / (DIM * PAD);
            int rem = j % (DIM * PAD);
            int e = rem / PAD, t = rem % PAD;
            B2[((long)b * DIM + e) * JPAD + JDIM + t] = z;
        }
    }
}

// ---------------------------------------------------------------------------
// fp32 -> fp16 convert
// ---------------------------------------------------------------------------
__global__ void cvt_h4(const float4* __restrict__ src,
                       __half2* __restrict__ dst, long n4)
{
    for (long i = (long)blockIdx.x * blockDim.x + threadIdx.x; i < n4;
         i += (long)gridDim.x * blockDim.x) {
        float4 v = src[i];
        dst[2 * i]     = __floats2half2_rn(v.x, v.y);
        dst[2 * i + 1] = __floats2half2_rn(v.z, v.w);
    }
}

// ---------------------------------------------------------------------------
// fused softmax(77-group) -> fp16 probs; zeros prob pad cols
// ---------------------------------------------------------------------------
__global__ __launch_bounds__(256) void softmax77h(const float* __restrict__ Smat,
                                                  __half* __restrict__ P)
{
    const int gw   = blockIdx.x * 8 + (threadIdx.x >> 5);
    const int lane = threadIdx.x & 31;
    const int row  = gw >> 3;
    const int h    = gw & 7;
    const long base = (long)row * JPAD + h * TOK;

    const float NEG = -1e30f;
    float x0 = Smat[base + lane];
    float x1 = Smat[base + 32 + lane];
    float x2 = (lane < 13) ? Smat[base + 64 + lane] : NEG;

    float m = fmaxf(x0, fmaxf(x1, x2));
    #pragma unroll
    for (int o = 16; o > 0; o >>= 1)
        m = fmaxf(m, __shfl_xor_sync(0xffffffffu, m, o));

    float e0 = expf(x0 - m);
    float e1 = expf(x1 - m);
    float e2 = (lane < 13) ? expf(x2 - m) : 0.f;
    float s = e0 + e1 + e2;
    #pragma unroll
    for (int o = 16; o > 0; o >>= 1)
        s += __shfl_xor_sync(0xffffffffu, s, o);

    const float inv = 1.f / s;
    P[base + lane]      = __float2half_rn(e0 * inv);
    P[base + 32 + lane] = __float2half_rn(e1 * inv);
    if (lane < 13) P[base + 64 + lane] = __float2half_rn(e2 * inv);
    if (h == 7 && lane < JPAD - JDIM)
        P[(long)row * JPAD + JDIM + lane] = __float2half_rn(0.f);
}

// ---------------------------------------------------------------------------
extern "C" void kernel_launch(void* const* d_in, const int* in_sizes, int n_in,
                              void* d_out, int out_size)
{
    const float* X  = (const float*)d_in[0];
    const float* E  = (const float*)d_in[1];
    const float* wq = (const float*)d_in[2];
    const float* wk = (const float*)d_in[3];
    const float* wv = (const float*)d_in[4];
    const float* wo = (const float*)d_in[5];
    const float* bo = (const float*)d_in[6];
    float* out = (float*)d_out;

    float *pK, *pV, *pS;
    __half *pXf, *pEf, *pWkf, *pWvf, *pA, *pB2, *pP;
    cudaGetSymbolAddress((void**)&pK,   g_K);
    cudaGetSymbolAddress((void**)&pV,   g_V);
    cudaGetSymbolAddress((void**)&pS,   g_S);
    cudaGetSymbolAddress((void**)&pXf,  g_Xf);
    cudaGetSymbolAddress((void**)&pEf,  g_Ef);
    cudaGetSymbolAddress((void**)&pWkf, g_wkf);
    cudaGetSymbolAddress((void**)&pWvf, g_wvf);
    cudaGetSymbolAddress((void**)&pA,   g_A);
    cudaGetSymbolAddress((void**)&pB2,  g_B2);
    cudaGetSymbolAddress((void**)&pP,   g_P);

    cudaFuncSetAttribute(mma_gemm, cudaFuncAttributeMaxDynamicSharedMemorySize,
                         MM_SMEM);

    // fp32 -> fp16 conversions (E, wk, wv, X)
    cvt_h4<<<1024, 256>>>((const float4*)E, (__half2*)pEf,
                          (long)ROWS_KV * CDIM / 4);
    cvt_h4<<<1024, 256>>>((const float4*)wk, (__half2*)pWkf,
                          (long)DIM * CDIM / 4);
    cvt_h4<<<1024, 256>>>((const float4*)wv, (__half2*)pWvf,
                          (long)DIM * CDIM / 4);
    cvt_h4<<<8192, 256>>>((const float4*)X, (__half2*)pXf,
                          (long)BATCH * SEQ * DIM / 4);

    // K/V projections via MMA: K[r][d] = E[r]·wk[d]  (rows padded to 1280)
    mma_gemm<<<dim3(DIM / 128, ROWS_KV_PAD / 128, 1), 256, MM_SMEM>>>(
        pEf, pWkf, pK, nullptr, CDIM, DIM, 0, 0, 0);
    mma_gemm<<<dim3(DIM / 128, ROWS_KV_PAD / 128, 1), 256, MM_SMEM>>>(
        pEf, pWvf, pV, nullptr, CDIM, DIM, 0, 0, 0);

    // folded operand matrices (fp16, K-major) — round-5 proven fold kernels
    fold_A<<<dim3(10, 8, 16), 256>>>(wq, pK, pA);
    fold_B<<<dim3(10, 8, 16), 256>>>(wo, pV, pB2);
    zero_pads<<<2048, 256>>>(pA, pB2);

    // scores: S[b][s][j] = sum_c X[s][c] * AfoldT[j][c]
    mma_gemm<<<dim3(JPAD / 128, SEQ / 128, BATCH), 256, MM_SMEM>>>(
        pXf, pA, pS, nullptr, DIM, JPAD,
        (long)SEQ * DIM, (long)JPAD * DIM, (long)SEQ * JPAD);

    // fused softmax -> fp16 probs
    softmax77h<<<BATCH * SEQ, 256>>>(pS, pP);

    // output: out[b][s][e] = sum_j P[s][j] * B2T[e][j] + bias[e]
    mma_gemm<<<dim3(DIM / 128, SEQ / 128, BATCH), 256, MM_SMEM>>>(
        pP, pB2, out, bo, JPAD, DIM,
        (long)SEQ * JPAD, (long)DIM * JPAD, (long)SEQ * DIM);
}

// round 8
// speedup vs baseline: 1.6311x; 1.1047x over previous
#include <cuda_runtime.h>
#include <cuda_fp16.h>
#include <math.h>
#include <stdint.h>

#define BATCH 16
#define SEQ   4096
#define DIM   1280
#define TOK   77
#define CDIM  768
#define HEADS 8
#define DHEAD 160
#define EPAD  192               /* DHEAD padded to KC multiple */
#define JDIM  616
#define JPAD  640
#define ROWS_KV 1232            /* BATCH*TOK */
#define ROWS_KV_PAD 1280

// ---------------------------------------------------------------------------
// Scratch (static device globals)
// ---------------------------------------------------------------------------
__device__ __align__(256) float  g_V  [ROWS_KV_PAD*DIM];
__device__ __align__(256) float  g_S  [(size_t)BATCH*SEQ*JPAD];     // scores fp32
__device__ __align__(256) __half g_Xf [(size_t)BATCH*SEQ*DIM];      // X fp16
__device__ __align__(256) __half g_Ef [(size_t)ROWS_KV_PAD*CDIM];   // E fp16 (padded rows)
__device__ __align__(256) __half g_wvf[(size_t)DIM*CDIM];           // wv fp16
__device__ __align__(256) __half g_wqT[(size_t)HEADS*DIM*EPAD];     // wq^T per head, e-padded
__device__ __align__(256) __half g_wkT[(size_t)HEADS*CDIM*EPAD];    // wk^T per head, e-padded
__device__ __align__(256) float  g_MqF[(size_t)HEADS*DIM*CDIM];     // Mq fp32
__device__ __align__(256) __half g_Mqh[(size_t)HEADS*DIM*CDIM];     // Mq fp16 (scaled)
__device__ __align__(256) __half g_A  [(size_t)BATCH*JPAD*DIM];     // AfoldT fp16
__device__ __align__(256) __half g_B2 [(size_t)BATCH*DIM*JPAD];     // B2T fp16
__device__ __align__(256) __half g_P  [(size_t)BATCH*SEQ*JPAD];     // probs fp16

// ---------------------------------------------------------------------------
// helpers
// ---------------------------------------------------------------------------
__device__ __forceinline__ uint32_t smem_u32(const void* p) {
    uint32_t a;
    asm("{ .reg .u64 t; cvta.to.shared.u64 t, %1; cvt.u32.u64 %0, t; }"
        : "=r"(a) : "l"(p));
    return a;
}

#define SWZ128(o) ((o) ^ (((o) >> 3) & 0x70))

__device__ __forceinline__ void cp16(uint32_t s, const void* g) {
    asm volatile("cp.async.cg.shared.global [%0], [%1], 16;" :: "r"(s), "l"(g));
}
#define CP_COMMIT() asm volatile("cp.async.commit_group;" ::: "memory")

__device__ __forceinline__ void ldsm4(uint32_t& r0, uint32_t& r1,
                                      uint32_t& r2, uint32_t& r3, uint32_t addr) {
    asm volatile("ldmatrix.sync.aligned.m8n8.x4.shared.b16 {%0,%1,%2,%3}, [%4];"
                 : "=r"(r0), "=r"(r1), "=r"(r2), "=r"(r3) : "r"(addr));
}

__device__ __forceinline__ void mma16816(float* c, uint32_t a0, uint32_t a1,
                                         uint32_t a2, uint32_t a3,
                                         uint32_t b0, uint32_t b1) {
    asm volatile(
        "mma.sync.aligned.m16n8k16.row.col.f32.f16.f16.f32 "
        "{%0,%1,%2,%3}, {%4,%5,%6,%7}, {%8,%9}, {%0,%1,%2,%3};"
        : "+f"(c[0]), "+f"(c[1]), "+f"(c[2]), "+f"(c[3])
        : "r"(a0), "r"(a1), "r"(a2), "r"(a3), "r"(b0), "r"(b1));
}

// ---------------------------------------------------------------------------
// warp-MMA GEMM:  C[m][n] = sum_k A[m][k]*B[n][k]   (single-pass fp16)
// CTA tile 128x128, 8 warps (4M x 2N), warp tile 32x64.
// ---------------------------------------------------------------------------
#define KC 64
#define TILE_B 16384
#define STAGE_B (2*TILE_B)
#define NSTAGE 3
#define MM_SMEM (NSTAGE*STAGE_B)

// Shared mainloop body as a macro-free pattern is verbose; we duplicate the
// kernel for the row-remap epilogue variant (mma_gemm_fa below).

__global__ __launch_bounds__(256, 2)
void mma_gemm(const __half* __restrict__ A, const __half* __restrict__ B,
              float* __restrict__ C, const float* __restrict__ bias,
              int K, int ldc, long sA, long sB, long sC)
{
    extern __shared__ __align__(1024) char smem[];
    const uint32_t sbase = smem_u32(smem);
    const int tid  = threadIdx.x;
    const int wid  = tid >> 5;
    const int lane = tid & 31;
    const int wm   = wid & 3;
    const int wn   = wid >> 2;

    const char* baseA = (const char*)(A + (long)blockIdx.z * sA
                                        + (long)(blockIdx.y * 128) * K);
    const char* baseB = (const char*)(B + (long)blockIdx.z * sB
                                        + (long)(blockIdx.x * 128) * K);

    uint32_t soff[4], goff[4];
    #pragma unroll
    for (int i = 0; i < 4; ++i) {
        int idx = tid + i * 256;
        int r = (idx >> 3) & 127;
        int u = idx & 7;
        soff[i] = SWZ128((uint32_t)(r * 128 + u * 16));
        goff[i] = (uint32_t)(r * (K * 2) + u * 16);
    }

    uint32_t aRowOff[2], aXor[2];
    #pragma unroll
    for (int mi = 0; mi < 2; ++mi) {
        int r = wm * 32 + mi * 16 + (lane & 15);
        aRowOff[mi] = (uint32_t)(r * 128);
        aXor[mi]    = (uint32_t)((r & 7) * 16);
    }
    const uint32_t aG = (uint32_t)((lane >> 4) * 16);

    uint32_t bRowOff[4], bXor[4];
    #pragma unroll
    for (int q = 0; q < 4; ++q) {
        int r = wn * 64 + q * 16 + (lane & 7) + ((lane >> 4) << 3);
        bRowOff[q] = (uint32_t)(r * 128);
        bXor[q]    = (uint32_t)((r & 7) * 16);
    }
    const uint32_t bG = (uint32_t)(((lane >> 3) & 1) * 16);

    float acc[2][8][4];
    #pragma unroll
    for (int mi = 0; mi < 2; ++mi)
        #pragma unroll
        for (int ni = 0; ni < 8; ++ni)
            #pragma unroll
            for (int e = 0; e < 4; ++e) acc[mi][ni][e] = 0.f;

    const int nk = K / KC;

    #pragma unroll
    for (int i = 0; i < 4; ++i) {
        cp16(sbase + soff[i],          baseA + goff[i]);
        cp16(sbase + TILE_B + soff[i], baseB + goff[i]);
    }
    CP_COMMIT();
    #pragma unroll
    for (int i = 0; i < 4; ++i) {
        cp16(sbase + STAGE_B + soff[i],          baseA + goff[i] + 128);
        cp16(sbase + STAGE_B + TILE_B + soff[i], baseB + goff[i] + 128);
    }
    CP_COMMIT();
    #pragma unroll
    for (int i = 0; i < 4; ++i) goff[i] += 256;

    for (int k = 0; k < nk; ++k) {
        if (k + 2 < nk) {
            const uint32_t sb = sbase + ((k + 2) % NSTAGE) * STAGE_B;
            #pragma unroll
            for (int i = 0; i < 4; ++i) {
                cp16(sb + soff[i],          baseA + goff[i]);
                cp16(sb + TILE_B + soff[i], baseB + goff[i]);
            }
            CP_COMMIT();
            #pragma unroll
            for (int i = 0; i < 4; ++i) goff[i] += 128;
            asm volatile("cp.async.wait_group 2;" ::: "memory");
        } else if (k + 1 < nk) {
            asm volatile("cp.async.wait_group 1;" ::: "memory");
        } else {
            asm volatile("cp.async.wait_group 0;" ::: "memory");
        }
        __syncthreads();

        const uint32_t aT = sbase + (k % NSTAGE) * STAGE_B;
        const uint32_t bT = aT + TILE_B;
        #pragma unroll
        for (int kk = 0; kk < 4; ++kk) {
            const uint32_t kb = (uint32_t)(kk * 32);
            uint32_t a[2][4];
            #pragma unroll
            for (int mi = 0; mi < 2; ++mi)
                ldsm4(a[mi][0], a[mi][1], a[mi][2], a[mi][3],
                      aT + aRowOff[mi] + ((aG + kb) ^ aXor[mi]));
            uint32_t b[4][4];
            #pragma unroll
            for (int q = 0; q < 4; ++q)
                ldsm4(b[q][0], b[q][1], b[q][2], b[q][3],
                      bT + bRowOff[q] + ((bG + kb) ^ bXor[q]));
            #pragma unroll
            for (int mi = 0; mi < 2; ++mi)
                #pragma unroll
                for (int q = 0; q < 4; ++q) {
                    mma16816(acc[mi][q * 2 + 0],
                             a[mi][0], a[mi][1], a[mi][2], a[mi][3],
                             b[q][0], b[q][1]);
                    mma16816(acc[mi][q * 2 + 1],
                             a[mi][0], a[mi][1], a[mi][2], a[mi][3],
                             b[q][2], b[q][3]);
                }
        }
        __syncthreads();
    }

    const int row0 = blockIdx.y * 128 + wm * 32 + (lane >> 2);
    const int col0 = blockIdx.x * 128 + wn * 64 + (lane & 3) * 2;
    float* Cb = C + (long)blockIdx.z * sC;
    #pragma unroll
    for (int mi = 0; mi < 2; ++mi) {
        #pragma unroll
        for (int ni = 0; ni < 8; ++ni) {
            const int r = row0 + mi * 16;
            const int c = col0 + ni * 8;
            float bx = 0.f, by = 0.f;
            if (bias) { bx = bias[c]; by = bias[c + 1]; }
            float2 v0 = make_float2(acc[mi][ni][0] + bx, acc[mi][ni][1] + by);
            float2 v1 = make_float2(acc[mi][ni][2] + bx, acc[mi][ni][3] + by);
            *reinterpret_cast<float2*>(Cb + (long)r * ldc + c)       = v0;
            *reinterpret_cast<float2*>(Cb + (long)(r + 8) * ldc + c) = v1;
        }
    }
}

// ---------------------------------------------------------------------------
// mma_gemm_fa: Afold GEMM with row-remap epilogue.
// C rows index (b,t) = b*77+t over E; output goes to
//   g_A[(b*JPAD + h*TOK + t)*DIM + c]  as fp16, guarded r < 1232.
// A = g_Ef (shared across z), B = g_Mqh + z*DIM*CDIM, K = CDIM.
// ---------------------------------------------------------------------------
__global__ __launch_bounds__(256, 2)
void mma_gemm_fa(const __half* __restrict__ A, const __half* __restrict__ B,
                 __half* __restrict__ Cdst)
{
    const int K = CDIM;
    extern __shared__ __align__(1024) char smem[];
    const uint32_t sbase = smem_u32(smem);
    const int tid  = threadIdx.x;
    const int wid  = tid >> 5;
    const int lane = tid & 31;
    const int wm   = wid & 3;
    const int wn   = wid >> 2;

    const char* baseA = (const char*)(A + (long)(blockIdx.y * 128) * K);
    const char* baseB = (const char*)(B + (long)blockIdx.z * DIM * CDIM
                                        + (long)(blockIdx.x * 128) * K);

    uint32_t soff[4], goff[4];
    #pragma unroll
    for (int i = 0; i < 4; ++i) {
        int idx = tid + i * 256;
        int r = (idx >> 3) & 127;
        int u = idx & 7;
        soff[i] = SWZ128((uint32_t)(r * 128 + u * 16));
        goff[i] = (uint32_t)(r * (K * 2) + u * 16);
    }

    uint32_t aRowOff[2], aXor[2];
    #pragma unroll
    for (int mi = 0; mi < 2; ++mi) {
        int r = wm * 32 + mi * 16 + (lane & 15);
        aRowOff[mi] = (uint32_t)(r * 128);
        aXor[mi]    = (uint32_t)((r & 7) * 16);
    }
    const uint32_t aG = (uint32_t)((lane >> 4) * 16);

    uint32_t bRowOff[4], bXor[4];
    #pragma unroll
    for (int q = 0; q < 4; ++q) {
        int r = wn * 64 + q * 16 + (lane & 7) + ((lane >> 4) << 3);
        bRowOff[q] = (uint32_t)(r * 128);
        bXor[q]    = (uint32_t)((r & 7) * 16);
    }
    const uint32_t bG = (uint32_t)(((lane >> 3) & 1) * 16);

    float acc[2][8][4];
    #pragma unroll
    for (int mi = 0; mi < 2; ++mi)
        #pragma unroll
        for (int ni = 0; ni < 8; ++ni)
            #pragma unroll
            for (int e = 0; e < 4; ++e) acc[mi][ni][e] = 0.f;

    const int nk = K / KC;

    #pragma unroll
    for (int i = 0; i < 4; ++i) {
        cp16(sbase + soff[i],          baseA + goff[i]);
        cp16(sbase + TILE_B + soff[i], baseB + goff[i]);
    }
    CP_COMMIT();
    #pragma unroll
    for (int i = 0; i < 4; ++i) {
        cp16(sbase + STAGE_B + soff[i],          baseA + goff[i] + 128);
        cp16(sbase + STAGE_B + TILE_B + soff[i], baseB + goff[i] + 128);
    }
    CP_COMMIT();
    #pragma unroll
    for (int i = 0; i < 4; ++i) goff[i] += 256;

    for (int k = 0; k < nk; ++k) {
        if (k + 2 < nk) {
            const uint32_t sb = sbase + ((k + 2) % NSTAGE) * STAGE_B;
            #pragma unroll
            for (int i = 0; i < 4; ++i) {
                cp16(sb + soff[i],          baseA + goff[i]);
                cp16(sb + TILE_B + soff[i], baseB + goff[i]);
            }
            CP_COMMIT();
            #pragma unroll
            for (int i = 0; i < 4; ++i) goff[i] += 128;
            asm volatile("cp.async.wait_group 2;" ::: "memory");
        } else if (k + 1 < nk) {
            asm volatile("cp.async.wait_group 1;" ::: "memory");
        } else {
            asm volatile("cp.async.wait_group 0;" ::: "memory");
        }
        __syncthreads();

        const uint32_t aT = sbase + (k % NSTAGE) * STAGE_B;
        const uint32_t bT = aT + TILE_B;
        #pragma unroll
        for (int kk = 0; kk < 4; ++kk) {
            const uint32_t kb = (uint32_t)(kk * 32);
            uint32_t a[2][4];
            #pragma unroll
            for (int mi = 0; mi < 2; ++mi)
                ldsm4(a[mi][0], a[mi][1], a[mi][2], a[mi][3],
                      aT + aRowOff[mi] + ((aG + kb) ^ aXor[mi]));
            uint32_t b[4][4];
            #pragma unroll
            for (int q = 0; q < 4; ++q)
                ldsm4(b[q][0], b[q][1], b[q][2], b[q][3],
                      bT + bRowOff[q] + ((bG + kb) ^ bXor[q]));
            #pragma unroll
            for (int mi = 0; mi < 2; ++mi)
                #pragma unroll
                for (int q = 0; q < 4; ++q) {
                    mma16816(acc[mi][q * 2 + 0],
                             a[mi][0], a[mi][1], a[mi][2], a[mi][3],
                             b[q][0], b[q][1]);
                    mma16816(acc[mi][q * 2 + 1],
                             a[mi][0], a[mi][1], a[mi][2], a[mi][3],
                             b[q][2], b[q][3]);
                }
        }
        __syncthreads();
    }

    // row-remap epilogue (fp16 output)
    const int h    = blockIdx.z;
    const int row0 = blockIdx.y * 128 + wm * 32 + (lane >> 2);
    const int col0 = blockIdx.x * 128 + wn * 64 + (lane & 3) * 2;
    #pragma unroll
    for (int mi = 0; mi < 2; ++mi) {
        #pragma unroll
        for (int sub = 0; sub < 2; ++sub) {
            const int r = row0 + mi * 16 + sub * 8;
            if (r >= ROWS_KV) continue;
            const int b = r / TOK;
            const int t = r - b * TOK;
            __half* dst = Cdst + ((long)b * JPAD + h * TOK + t) * DIM;
            #pragma unroll
            for (int ni = 0; ni < 8; ++ni) {
                const int c = col0 + ni * 8;
                __half2 v = __floats2half2_rn(acc[mi][ni][sub * 2 + 0],
                                              acc[mi][ni][sub * 2 + 1]);
                *reinterpret_cast<__half2*>(dst + c) = v;
            }
        }
    }
}

// ---------------------------------------------------------------------------
// transpose+pad: src[h*160+e][RD] fp32 -> dst[h][RD][EPAD] fp16 (e>=160 -> 0)
// block 256 (32x8), grid (RD/32, EPAD/32, HEADS)
// ---------------------------------------------------------------------------
__global__ __launch_bounds__(256) void transpose_pad(
    const float* __restrict__ src, __half* __restrict__ dst, int RD)
{
    __shared__ float tile[32][33];
    const int tx = threadIdx.x & 31;
    const int ty = threadIdx.x >> 5;
    const int r0 = blockIdx.x * 32;
    const int e0 = blockIdx.y * 32;
    const int h  = blockIdx.z;
    #pragma unroll
    for (int i = 0; i < 4; ++i) {
        const int e = e0 + ty + i * 8;
        float v = 0.f;
        if (e < DHEAD) v = src[(long)(h * DHEAD + e) * RD + r0 + tx];
        tile[ty + i * 8][tx] = v;
    }
    __syncthreads();
    #pragma unroll
    for (int i = 0; i < 4; ++i) {
        const int r = r0 + ty + i * 8;
        dst[((long)h * RD + r) * EPAD + e0 + tx] =
            __float2half_rn(tile[tx][ty + i * 8]);
    }
}

// ---------------------------------------------------------------------------
// fold_B (round-5 proven): B2T[b][e2][h*77+t] = sum_e V[b,t][he]*wout[e2][he]
// ---------------------------------------------------------------------------
__global__ __launch_bounds__(256) void fold_B(
    const float* __restrict__ wout, const float* __restrict__ Vmat,
    __half* __restrict__ outH)
{
    const int b = blockIdx.z, hd = blockIdx.y;
    const int n0 = blockIdx.x * 128;
    __shared__ float Vs[16][80];
    __shared__ float Ws[16][128];

    const int tid  = threadIdx.x;
    const int tcid = tid & 15;
    const int ttid = tid >> 4;

    float acc[5][8];
    #pragma unroll
    for (int j = 0; j < 5; j++)
        #pragma unroll
        for (int i = 0; i < 8; i++) acc[j][i] = 0.f;

    for (int e0 = 0; e0 < DHEAD; e0 += 16) {
        for (int idx = tid; idx < 128 * 16; idx += 256) {
            const int n = idx >> 4, k = idx & 15;
            Ws[k][n] = wout[(long)(n0 + n) * DIM + hd * DHEAD + e0 + k];
        }
        for (int idx = tid; idx < TOK * 16; idx += 256) {
            const int t = idx >> 4, k = idx & 15;
            Vs[k][t] = Vmat[(long)(b * TOK + t) * DIM + hd * DHEAD + e0 + k];
        }
        for (int idx = tid; idx < 3 * 16; idx += 256)
            Vs[idx & 15][TOK + (idx >> 4)] = 0.f;
        __syncthreads();
        #pragma unroll
        for (int k = 0; k < 16; k++) {
            float vv[5], ww[8];
            #pragma unroll
            for (int j = 0; j < 5; j++) vv[j] = Vs[k][ttid * 5 + j];
            #pragma unroll
            for (int i = 0; i < 8; i++) ww[i] = Ws[k][tcid * 8 + i];
            #pragma unroll
            for (int j = 0; j < 5; j++)
                #pragma unroll
                for (int i = 0; i < 8; i++)
                    acc[j][i] = fmaf(vv[j], ww[i], acc[j][i]);
        }
        __syncthreads();
    }
    #pragma unroll
    for (int j = 0; j < 5; j++) {
        const int t = ttid * 5 + j;
        if (t >= TOK) continue;
        #pragma unroll
        for (int i = 0; i < 8; i++) {
            const int n = n0 + tcid * 8 + i;
            long off = ((long)b * DIM + n) * JPAD + hd * TOK + t;
            outH[off] = __float2half_rn(acc[j][i]);
        }
    }
}

// ---------------------------------------------------------------------------
// zero pads: Afold rows [616,640), B2T cols [616,640), Ef rows [1232,1280)
// ---------------------------------------------------------------------------
__global__ void zero_pads(__half* A, __half* B2, __half* Ef)
{
    const int PAD = JPAD - JDIM;               // 24
    const int n1 = BATCH * PAD * DIM;
    const int n2 = BATCH * DIM * PAD;
    const int n3 = (ROWS_KV_PAD - ROWS_KV) * CDIM;
    const __half z = __float2half_rn(0.f);
    for (int i = blockIdx.x * blockDim.x + threadIdx.x; i < n1 + n2 + n3;
         i += gridDim.x * blockDim.x) {
        if (i < n1) {
            int b = i / (PAD * DIM);
            int rem = i % (PAD * DIM);
            int r = rem / DIM, c = rem % DIM;
            A[((long)b * JPAD + JDIM + r) * DIM + c] = z;
        } else if (i < n1 + n2) {
            int j = i - n1;
            int b = j / (DIM * PAD);
            int rem = j % (DIM * PAD);
            int e = rem / PAD, t = rem % PAD;
            B2[((long)b * DIM + e) * JPAD + JDIM + t] = z;
        } else {
            Ef[(long)ROWS_KV * CDIM + (i - n1 - n2)] = z;
        }
    }
}

// ---------------------------------------------------------------------------
// fp32 -> fp16 convert (optional scale)
// ---------------------------------------------------------------------------
__global__ void cvt_h4(const float4* __restrict__ src,
                       __half2* __restrict__ dst, long n4, float scale)
{
    for (long i = (long)blockIdx.x * blockDim.x + threadIdx.x; i < n4;
         i += (long)gridDim.x * blockDim.x) {
        float4 v = src[i];
        dst[2 * i]     = __floats2half2_rn(v.x * scale, v.y * scale);
        dst[2 * i + 1] = __floats2half2_rn(v.z * scale, v.w * scale);
    }
}

// ---------------------------------------------------------------------------
// fused softmax(77-group) -> fp16 probs; zeros prob pad cols
// ---------------------------------------------------------------------------
__global__ __launch_bounds__(256) void softmax77h(const float* __restrict__ Smat,
                                                  __half* __restrict__ P)
{
    const int gw   = blockIdx.x * 8 + (threadIdx.x >> 5);
    const int lane = threadIdx.x & 31;
    const int row  = gw >> 3;
    const int h    = gw & 7;
    const long base = (long)row * JPAD + h * TOK;

    const float NEG = -1e30f;
    float x0 = Smat[base + lane];
    float x1 = Smat[base + 32 + lane];
    float x2 = (lane < 13) ? Smat[base + 64 + lane] : NEG;

    float m = fmaxf(x0, fmaxf(x1, x2));
    #pragma unroll
    for (int o = 16; o > 0; o >>= 1)
        m = fmaxf(m, __shfl_xor_sync(0xffffffffu, m, o));

    float e0 = expf(x0 - m);
    float e1 = expf(x1 - m);
    float e2 = (lane < 13) ? expf(x2 - m) : 0.f;
    float s = e0 + e1 + e2;
    #pragma unroll
    for (int o = 16; o > 0; o >>= 1)
        s += __shfl_xor_sync(0xffffffffu, s, o);

    const float inv = 1.f / s;
    P[base + lane]      = __float2half_rn(e0 * inv);
    P[base + 32 + lane] = __float2half_rn(e1 * inv);
    if (lane < 13) P[base + 64 + lane] = __float2half_rn(e2 * inv);
    if (h == 7 && lane < JPAD - JDIM)
        P[(long)row * JPAD + JDIM + lane] = __float2half_rn(0.f);
}

// ---------------------------------------------------------------------------
extern "C" void kernel_launch(void* const* d_in, const int* in_sizes, int n_in,
                              void* d_out, int out_size)
{
    const float* X  = (const float*)d_in[0];
    const float* E  = (const float*)d_in[1];
    const float* wq = (const float*)d_in[2];
    const float* wk = (const float*)d_in[3];
    const float* wv = (const float*)d_in[4];
    const float* wo = (const float*)d_in[5];
    const float* bo = (const float*)d_in[6];
    float* out = (float*)d_out;

    float *pV, *pS, *pMqF;
    __half *pXf, *pEf, *pWvf, *pWqT, *pWkT, *pMqh, *pA, *pB2, *pP;
    cudaGetSymbolAddress((void**)&pV,   g_V);
    cudaGetSymbolAddress((void**)&pS,   g_S);
    cudaGetSymbolAddress((void**)&pMqF, g_MqF);
    cudaGetSymbolAddress((void**)&pXf,  g_Xf);
    cudaGetSymbolAddress((void**)&pEf,  g_Ef);
    cudaGetSymbolAddress((void**)&pWvf, g_wvf);
    cudaGetSymbolAddress((void**)&pWqT, g_wqT);
    cudaGetSymbolAddress((void**)&pWkT, g_wkT);
    cudaGetSymbolAddress((void**)&pMqh, g_Mqh);
    cudaGetSymbolAddress((void**)&pA,   g_A);
    cudaGetSymbolAddress((void**)&pB2,  g_B2);
    cudaGetSymbolAddress((void**)&pP,   g_P);

    cudaFuncSetAttribute(mma_gemm, cudaFuncAttributeMaxDynamicSharedMemorySize,
                         MM_SMEM);
    cudaFuncSetAttribute(mma_gemm_fa, cudaFuncAttributeMaxDynamicSharedMemorySize,
                         MM_SMEM);

    const float scale = 0.07905694150420949f;   // 160^-0.5

    // fp32 -> fp16 conversions
    cvt_h4<<<1024, 256>>>((const float4*)E, (__half2*)pEf,
                          (long)ROWS_KV * CDIM / 4, 1.f);
    cvt_h4<<<1024, 256>>>((const float4*)wv, (__half2*)pWvf,
                          (long)DIM * CDIM / 4, 1.f);
    cvt_h4<<<8192, 256>>>((const float4*)X, (__half2*)pXf,
                          (long)BATCH * SEQ * DIM / 4, 1.f);

    // transposed, e-padded head slices of wq / wk
    transpose_pad<<<dim3(DIM / 32, EPAD / 32, HEADS), 256>>>(wq, pWqT, DIM);
    transpose_pad<<<dim3(CDIM / 32, EPAD / 32, HEADS), 256>>>(wk, pWkT, CDIM);

    // Mq[h][c][f] = sum_e wq[he][c] * wk[he][f]   (fp32 out)
    mma_gemm<<<dim3(CDIM / 128, DIM / 128, HEADS), 256, MM_SMEM>>>(
        pWqT, pWkT, pMqF, nullptr, EPAD, CDIM,
        (long)DIM * EPAD, (long)CDIM * EPAD, (long)DIM * CDIM);

    // Mq -> fp16 with d^-0.5 folded in
    cvt_h4<<<2048, 256>>>((const float4*)pMqF, (__half2*)pMqh,
                          (long)HEADS * DIM * CDIM / 4, scale);

    // V projection: V[r][d] = E[r]·wv[d]
    mma_gemm<<<dim3(DIM / 128, ROWS_KV_PAD / 128, 1), 256, MM_SMEM>>>(
        pEf, pWvf, pV, nullptr, CDIM, DIM, 0, 0, 0);

    // zero Ef pad rows (before fa GEMM reads them), Afold/B2 pads (written
    // regions are disjoint from fold outputs, order vs folds irrelevant)
    zero_pads<<<2048, 256>>>(pA, pB2, pEf);

    // Afold via GEMM: rows (b,t) of E  x  Mq_h  -> Afold[b][h*77+t][c]
    mma_gemm_fa<<<dim3(DIM / 128, ROWS_KV_PAD / 128, HEADS), 256, MM_SMEM>>>(
        pEf, pMqh, pA);

    // fold_B (SIMT, proven)
    fold_B<<<dim3(10, 8, 16), 256>>>(wo, pV, pB2);

    // scores: S[b][s][j] = sum_c X[s][c] * AfoldT[j][c]
    mma_gemm<<<dim3(JPAD / 128, SEQ / 128, BATCH), 256, MM_SMEM>>>(
        pXf, pA, pS, nullptr, DIM, JPAD,
        (long)SEQ * DIM, (long)JPAD * DIM, (long)SEQ * JPAD);

    // fused softmax -> fp16 probs
    softmax77h<<<BATCH * SEQ, 256>>>(pS, pP);

    // output: out[b][s][e] = sum_j P[s][j] * B2T[e][j] + bias[e]
    mma_gemm<<<dim3(DIM / 128, SEQ / 128, BATCH), 256, MM_SMEM>>>(
        pP, pB2, out, bo, JPAD, DIM,
        (long)SEQ * JPAD, (long)DIM * JPAD, (long)SEQ * DIM);
}

// round 9
// speedup vs baseline: 1.9339x; 1.1857x over previous
#include <cuda_runtime.h>
#include <cuda_fp16.h>
#include <math.h>
#include <stdint.h>

#define BATCH 16
#define SEQ   4096
#define DIM   1280
#define TOK   77
#define CDIM  768
#define HEADS 8
#define DHEAD 160
#define EPAD  192
#define JDIM  616
#define JPAD  640
#define ROWS_KV 1232
#define ROWS_KV_PAD 1280

// ---------------------------------------------------------------------------
// Scratch (static device globals)
// ---------------------------------------------------------------------------
__device__ __align__(256) float  g_S  [(size_t)BATCH*SEQ*JPAD];     // scores fp32
__device__ __align__(256) __half g_Xf [(size_t)BATCH*SEQ*DIM];      // X fp16
__device__ __align__(256) __half g_Ef [(size_t)ROWS_KV_PAD*CDIM];   // E fp16 (padded)
__device__ __align__(256) __half g_wqT[(size_t)HEADS*DIM*EPAD];     // wq^T/head, e-pad
__device__ __align__(256) __half g_wkT[(size_t)HEADS*CDIM*EPAD];    // wk^T/head, e-pad
__device__ __align__(256) __half g_wvT[(size_t)HEADS*CDIM*EPAD];    // wv^T/head, e-pad
__device__ __align__(256) __half g_woS[(size_t)HEADS*DIM*EPAD];     // wo head-slice
__device__ __align__(256) float  g_MqF[(size_t)HEADS*DIM*CDIM];
__device__ __align__(256) __half g_Mqh[(size_t)HEADS*DIM*CDIM];
__device__ __align__(256) float  g_MoF[(size_t)HEADS*DIM*CDIM];
__device__ __align__(256) __half g_Moh[(size_t)HEADS*DIM*CDIM];
__device__ __align__(256) __half g_A  [(size_t)BATCH*JPAD*DIM];     // AfoldT fp16
__device__ __align__(256) __half g_B2 [(size_t)BATCH*DIM*JPAD];     // B2T fp16
__device__ __align__(256) __half g_P  [(size_t)BATCH*SEQ*JPAD];     // probs fp16

// ---------------------------------------------------------------------------
// helpers
// ---------------------------------------------------------------------------
__device__ __forceinline__ uint32_t smem_u32(const void* p) {
    uint32_t a;
    asm("{ .reg .u64 t; cvta.to.shared.u64 t, %1; cvt.u32.u64 %0, t; }"
        : "=r"(a) : "l"(p));
    return a;
}

#define SWZ128(o) ((o) ^ (((o) >> 3) & 0x70))

__device__ __forceinline__ void cp16(uint32_t s, const void* g) {
    asm volatile("cp.async.cg.shared.global [%0], [%1], 16;" :: "r"(s), "l"(g));
}
#define CP_COMMIT() asm volatile("cp.async.commit_group;" ::: "memory")

__device__ __forceinline__ void ldsm4(uint32_t& r0, uint32_t& r1,
                                      uint32_t& r2, uint32_t& r3, uint32_t addr) {
    asm volatile("ldmatrix.sync.aligned.m8n8.x4.shared.b16 {%0,%1,%2,%3}, [%4];"
                 : "=r"(r0), "=r"(r1), "=r"(r2), "=r"(r3) : "r"(addr));
}

__device__ __forceinline__ void mma16816(float* c, uint32_t a0, uint32_t a1,
                                         uint32_t a2, uint32_t a3,
                                         uint32_t b0, uint32_t b1) {
    asm volatile(
        "mma.sync.aligned.m16n8k16.row.col.f32.f16.f16.f32 "
        "{%0,%1,%2,%3}, {%4,%5,%6,%7}, {%8,%9}, {%0,%1,%2,%3};"
        : "+f"(c[0]), "+f"(c[1]), "+f"(c[2]), "+f"(c[3])
        : "r"(a0), "r"(a1), "r"(a2), "r"(a3), "r"(b0), "r"(b1));
}

// ---------------------------------------------------------------------------
// Common GEMM config
// ---------------------------------------------------------------------------
#define KC 64
#define TILE_B 16384
#define STAGE_B (2*TILE_B)
#define NSTAGE 3
#define MM_SMEM (NSTAGE*STAGE_B)

// Mainloop shared by all three GEMM kernels (same body, different epilogues),
// expressed as a macro to guarantee identical codegen.
#define MMA_MAINLOOP(baseA_, baseB_, K_)                                        \
    uint32_t soff[4], goff[4];                                                  \
    _Pragma("unroll")                                                           \
    for (int i = 0; i < 4; ++i) {                                               \
        int idx = tid + i * 256;                                                \
        int r = (idx >> 3) & 127;                                               \
        int u = idx & 7;                                                        \
        soff[i] = SWZ128((uint32_t)(r * 128 + u * 16));                         \
        goff[i] = (uint32_t)(r * ((K_) * 2) + u * 16);                          \
    }                                                                           \
    uint32_t aRowOff[2], aXor[2];                                               \
    _Pragma("unroll")                                                           \
    for (int mi = 0; mi < 2; ++mi) {                                            \
        int r = wm * 32 + mi * 16 + (lane & 15);                                \
        aRowOff[mi] = (uint32_t)(r * 128);                                      \
        aXor[mi]    = (uint32_t)((r & 7) * 16);                                 \
    }                                                                           \
    const uint32_t aG = (uint32_t)((lane >> 4) * 16);                           \
    uint32_t bRowOff[4], bXor[4];                                               \
    _Pragma("unroll")                                                           \
    for (int q = 0; q < 4; ++q) {                                               \
        int r = wn * 64 + q * 16 + (lane & 7) + ((lane >> 4) << 3);             \
        bRowOff[q] = (uint32_t)(r * 128);                                       \
        bXor[q]    = (uint32_t)((r & 7) * 16);                                  \
    }                                                                           \
    const uint32_t bG = (uint32_t)(((lane >> 3) & 1) * 16);                     \
    float acc[2][8][4];                                                         \
    _Pragma("unroll")                                                           \
    for (int mi = 0; mi < 2; ++mi)                                              \
        _Pragma("unroll")                                                       \
        for (int ni = 0; ni < 8; ++ni)                                          \
            _Pragma("unroll")                                                   \
            for (int e = 0; e < 4; ++e) acc[mi][ni][e] = 0.f;                   \
    const int nk = (K_) / KC;                                                   \
    _Pragma("unroll")                                                           \
    for (int i = 0; i < 4; ++i) {                                               \
        cp16(sbase + soff[i],          (baseA_) + goff[i]);                     \
        cp16(sbase + TILE_B + soff[i], (baseB_) + goff[i]);                     \
    }                                                                           \
    CP_COMMIT();                                                                \
    _Pragma("unroll")                                                           \
    for (int i = 0; i < 4; ++i) {                                               \
        cp16(sbase + STAGE_B + soff[i],          (baseA_) + goff[i] + 128);     \
        cp16(sbase + STAGE_B + TILE_B + soff[i], (baseB_) + goff[i] + 128);     \
    }                                                                           \
    CP_COMMIT();                                                                \
    _Pragma("unroll")                                                           \
    for (int i = 0; i < 4; ++i) goff[i] += 256;                                 \
    for (int k = 0; k < nk; ++k) {                                              \
        if (k + 2 < nk) {                                                       \
            const uint32_t sb = sbase + ((k + 2) % NSTAGE) * STAGE_B;           \
            _Pragma("unroll")                                                   \
            for (int i = 0; i < 4; ++i) {                                       \
                cp16(sb + soff[i],          (baseA_) + goff[i]);                \
                cp16(sb + TILE_B + soff[i], (baseB_) + goff[i]);                \
            }                                                                   \
            CP_COMMIT();                                                        \
            _Pragma("unroll")                                                   \
            for (int i = 0; i < 4; ++i) goff[i] += 128;                         \
            asm volatile("cp.async.wait_group 2;" ::: "memory");                \
        } else if (k + 1 < nk) {                                                \
            asm volatile("cp.async.wait_group 1;" ::: "memory");                \
        } else {                                                                \
            asm volatile("cp.async.wait_group 0;" ::: "memory");                \
        }                                                                       \
        __syncthreads();                                                        \
        const uint32_t aT = sbase + (k % NSTAGE) * STAGE_B;                     \
        const uint32_t bT = aT + TILE_B;                                        \
        _Pragma("unroll")                                                       \
        for (int kk = 0; kk < 4; ++kk) {                                        \
            const uint32_t kb = (uint32_t)(kk * 32);                            \
            uint32_t a[2][4];                                                   \
            _Pragma("unroll")                                                   \
            for (int mi = 0; mi < 2; ++mi)                                      \
                ldsm4(a[mi][0], a[mi][1], a[mi][2], a[mi][3],                   \
                      aT + aRowOff[mi] + ((aG + kb) ^ aXor[mi]));               \
            uint32_t b[4][4];                                                   \
            _Pragma("unroll")                                                   \
            for (int q = 0; q < 4; ++q)                                         \
                ldsm4(b[q][0], b[q][1], b[q][2], b[q][3],                       \
                      bT + bRowOff[q] + ((bG + kb) ^ bXor[q]));                 \
            _Pragma("unroll")                                                   \
            for (int mi = 0; mi < 2; ++mi)                                      \
                _Pragma("unroll")                                               \
                for (int q = 0; q < 4; ++q) {                                   \
                    mma16816(acc[mi][q * 2 + 0],                                \
                             a[mi][0], a[mi][1], a[mi][2], a[mi][3],            \
                             b[q][0], b[q][1]);                                 \
                    mma16816(acc[mi][q * 2 + 1],                                \
                             a[mi][0], a[mi][1], a[mi][2], a[mi][3],            \
                             b[q][2], b[q][3]);                                 \
                }                                                               \
        }                                                                       \
        __syncthreads();                                                        \
    }

// ---------------------------------------------------------------------------
// mma_gemm: fp32 output, optional bias
// ---------------------------------------------------------------------------
__global__ __launch_bounds__(256, 2)
void mma_gemm(const __half* __restrict__ A, const __half* __restrict__ B,
              float* __restrict__ C, const float* __restrict__ bias,
              int K, int ldc, long sA, long sB, long sC)
{
    extern __shared__ __align__(1024) char smem[];
    const uint32_t sbase = smem_u32(smem);
    const int tid  = threadIdx.x;
    const int wid  = tid >> 5;
    const int lane = tid & 31;
    const int wm   = wid & 3;
    const int wn   = wid >> 2;

    const char* baseA = (const char*)(A + (long)blockIdx.z * sA
                                        + (long)(blockIdx.y * 128) * K);
    const char* baseB = (const char*)(B + (long)blockIdx.z * sB
                                        + (long)(blockIdx.x * 128) * K);

    MMA_MAINLOOP(baseA, baseB, K)

    const int row0 = blockIdx.y * 128 + wm * 32 + (lane >> 2);
    const int col0 = blockIdx.x * 128 + wn * 64 + (lane & 3) * 2;
    float* Cb = C + (long)blockIdx.z * sC;
    #pragma unroll
    for (int mi = 0; mi < 2; ++mi) {
        #pragma unroll
        for (int ni = 0; ni < 8; ++ni) {
            const int r = row0 + mi * 16;
            const int c = col0 + ni * 8;
            float bx = 0.f, by = 0.f;
            if (bias) { bx = bias[c]; by = bias[c + 1]; }
            float2 v0 = make_float2(acc[mi][ni][0] + bx, acc[mi][ni][1] + by);
            float2 v1 = make_float2(acc[mi][ni][2] + bx, acc[mi][ni][3] + by);
            *reinterpret_cast<float2*>(Cb + (long)r * ldc + c)       = v0;
            *reinterpret_cast<float2*>(Cb + (long)(r + 8) * ldc + c) = v1;
        }
    }
}

// ---------------------------------------------------------------------------
// mma_gemm_fa: Afold GEMM, row-remap epilogue.
// rows = (b,t) over E; dst g_A[(b*JPAD + h*TOK + t)*DIM + c] fp16.
// ---------------------------------------------------------------------------
__global__ __launch_bounds__(256, 2)
void mma_gemm_fa(const __half* __restrict__ A, const __half* __restrict__ B,
                 __half* __restrict__ Cdst)
{
    const int K = CDIM;
    extern __shared__ __align__(1024) char smem[];
    const uint32_t sbase = smem_u32(smem);
    const int tid  = threadIdx.x;
    const int wid  = tid >> 5;
    const int lane = tid & 31;
    const int wm   = wid & 3;
    const int wn   = wid >> 2;

    const char* baseA = (const char*)(A + (long)(blockIdx.y * 128) * K);
    const char* baseB = (const char*)(B + (long)blockIdx.z * DIM * CDIM
                                        + (long)(blockIdx.x * 128) * K);

    MMA_MAINLOOP(baseA, baseB, K)

    const int h    = blockIdx.z;
    const int row0 = blockIdx.y * 128 + wm * 32 + (lane >> 2);
    const int col0 = blockIdx.x * 128 + wn * 64 + (lane & 3) * 2;
    #pragma unroll
    for (int mi = 0; mi < 2; ++mi) {
        #pragma unroll
        for (int sub = 0; sub < 2; ++sub) {
            const int r = row0 + mi * 16 + sub * 8;
            if (r >= ROWS_KV) continue;
            const int b = r / TOK;
            const int t = r - b * TOK;
            __half* dst = Cdst + ((long)b * JPAD + h * TOK + t) * DIM;
            #pragma unroll
            for (int ni = 0; ni < 8; ++ni) {
                const int c = col0 + ni * 8;
                __half2 v = __floats2half2_rn(acc[mi][ni][sub * 2 + 0],
                                              acc[mi][ni][sub * 2 + 1]);
                *reinterpret_cast<__half2*>(dst + c) = v;
            }
        }
    }
}

// ---------------------------------------------------------------------------
// mma_gemm_fb: B2 GEMM, column-remap epilogue.
// A = Mo_h [DIM][CDIM], B = Ef rows (b,t); dst g_B2[(b*DIM + e2)*JPAD + h*TOK + t].
// ---------------------------------------------------------------------------
__global__ __launch_bounds__(256, 2)
void mma_gemm_fb(const __half* __restrict__ A, const __half* __restrict__ B,
                 __half* __restrict__ Cdst)
{
    const int K = CDIM;
    extern __shared__ __align__(1024) char smem[];
    const uint32_t sbase = smem_u32(smem);
    const int tid  = threadIdx.x;
    const int wid  = tid >> 5;
    const int lane = tid & 31;
    const int wm   = wid & 3;
    const int wn   = wid >> 2;

    const char* baseA = (const char*)(A + (long)blockIdx.z * DIM * CDIM
                                        + (long)(blockIdx.y * 128) * K);
    const char* baseB = (const char*)(B + (long)(blockIdx.x * 128) * K);

    MMA_MAINLOOP(baseA, baseB, K)

    const int h    = blockIdx.z;
    const int row0 = blockIdx.y * 128 + wm * 32 + (lane >> 2);   // e2
    const int col0 = blockIdx.x * 128 + wn * 64 + (lane & 3) * 2; // (b,t)
    #pragma unroll
    for (int mi = 0; mi < 2; ++mi) {
        #pragma unroll
        for (int ni = 0; ni < 8; ++ni) {
            #pragma unroll
            for (int e = 0; e < 4; ++e) {
                const int r = row0 + mi * 16 + (e >> 1) * 8;
                const int c = col0 + ni * 8 + (e & 1);
                if (c < ROWS_KV) {
                    const int b = c / TOK;
                    const int t = c - b * TOK;
                    Cdst[((long)b * DIM + r) * JPAD + h * TOK + t] =
                        __float2half_rn(acc[mi][ni][e]);
                }
            }
        }
    }
}

// ---------------------------------------------------------------------------
// transpose+pad: src[h*160+e][RD] fp32 -> dst[h][RD][EPAD] fp16 (e>=160 -> 0)
// ---------------------------------------------------------------------------
__global__ __launch_bounds__(256) void transpose_pad(
    const float* __restrict__ src, __half* __restrict__ dst, int RD)
{
    __shared__ float tile[32][33];
    const int tx = threadIdx.x & 31;
    const int ty = threadIdx.x >> 5;
    const int r0 = blockIdx.x * 32;
    const int e0 = blockIdx.y * 32;
    const int h  = blockIdx.z;
    #pragma unroll
    for (int i = 0; i < 4; ++i) {
        const int e = e0 + ty + i * 8;
        float v = 0.f;
        if (e < DHEAD) v = src[(long)(h * DHEAD + e) * RD + r0 + tx];
        tile[ty + i * 8][tx] = v;
    }
    __syncthreads();
    #pragma unroll
    for (int i = 0; i < 4; ++i) {
        const int r = r0 + ty + i * 8;
        dst[((long)h * RD + r) * EPAD + e0 + tx] =
            __float2half_rn(tile[tx][ty + i * 8]);
    }
}

// ---------------------------------------------------------------------------
// woslice: dst[h][e2][ep] fp16 = wo[e2][h*160+ep] (ep>=160 -> 0)
// ---------------------------------------------------------------------------
__global__ void woslice(const float* __restrict__ wo, __half* __restrict__ dst)
{
    const long n = (long)HEADS * DIM * EPAD;
    for (long i = (long)blockIdx.x * blockDim.x + threadIdx.x; i < n;
         i += (long)gridDim.x * blockDim.x) {
        int ep = (int)(i % EPAD);
        long he2 = i / EPAD;
        int e2 = (int)(he2 % DIM);
        int h  = (int)(he2 / DIM);
        float v = (ep < DHEAD) ? wo[(long)e2 * DIM + h * DHEAD + ep] : 0.f;
        dst[i] = __float2half_rn(v);
    }
}

// ---------------------------------------------------------------------------
// zero pads: Afold rows [616,640), B2T cols [616,640), Ef rows [1232,1280)
// ---------------------------------------------------------------------------
__global__ void zero_pads(__half* A, __half* B2, __half* Ef)
{
    const int PAD = JPAD - JDIM;
    const int n1 = BATCH * PAD * DIM;
    const int n2 = BATCH * DIM * PAD;
    const int n3 = (ROWS_KV_PAD - ROWS_KV) * CDIM;
    const __half z = __float2half_rn(0.f);
    for (int i = blockIdx.x * blockDim.x + threadIdx.x; i < n1 + n2 + n3;
         i += gridDim.x * blockDim.x) {
        if (i < n1) {
            int b = i / (PAD * DIM);
            int rem = i % (PAD * DIM);
            int r = rem / DIM, c = rem % DIM;
            A[((long)b * JPAD + JDIM + r) * DIM + c] = z;
        } else if (i < n1 + n2) {
            int j = i - n1;
            int b = j / (DIM * PAD);
            int rem = j % (DIM * PAD);
            int e = rem / PAD, t = rem % PAD;
            B2[((long)b * DIM + e) * JPAD + JDIM + t] = z;
        } else {
            Ef[(long)ROWS_KV * CDIM + (i - n1 - n2)] = z;
        }
    }
}

// ---------------------------------------------------------------------------
// fp32 -> fp16 convert (optional scale)
// ---------------------------------------------------------------------------
__global__ void cvt_h4(const float4* __restrict__ src,
                       __half2* __restrict__ dst, long n4, float scale)
{
    for (long i = (long)blockIdx.x * blockDim.x + threadIdx.x; i < n4;
         i += (long)gridDim.x * blockDim.x) {
        float4 v = src[i];
        dst[2 * i]     = __floats2half2_rn(v.x * scale, v.y * scale);
        dst[2 * i + 1] = __floats2half2_rn(v.z * scale, v.w * scale);
    }
}

// ---------------------------------------------------------------------------
// fused softmax(77-group) -> fp16 probs; zeros prob pad cols
// ---------------------------------------------------------------------------
__global__ __launch_bounds__(256) void softmax77h(const float* __restrict__ Smat,
                                                  __half* __restrict__ P)
{
    const int gw   = blockIdx.x * 8 + (threadIdx.x >> 5);
    const int lane = threadIdx.x & 31;
    const int row  = gw >> 3;
    const int h    = gw & 7;
    const long base = (long)row * JPAD + h * TOK;

    const float NEG = -1e30f;
    float x0 = Smat[base + lane];
    float x1 = Smat[base + 32 + lane];
    float x2 = (lane < 13) ? Smat[base + 64 + lane] : NEG;

    float m = fmaxf(x0, fmaxf(x1, x2));
    #pragma unroll
    for (int o = 16; o > 0; o >>= 1)
        m = fmaxf(m, __shfl_xor_sync(0xffffffffu, m, o));

    float e0 = expf(x0 - m);
    float e1 = expf(x1 - m);
    float e2 = (lane < 13) ? expf(x2 - m) : 0.f;
    float s = e0 + e1 + e2;
    #pragma unroll
    for (int o = 16; o > 0; o >>= 1)
        s += __shfl_xor_sync(0xffffffffu, s, o);

    const float inv = 1.f / s;
    P[base + lane]      = __float2half_rn(e0 * inv);
    P[base + 32 + lane] = __float2half_rn(e1 * inv);
    if (lane < 13) P[base + 64 + lane] = __float2half_rn(e2 * inv);
    if (h == 7 && lane < JPAD - JDIM)
        P[(long)row * JPAD + JDIM + lane] = __float2half_rn(0.f);
}

// ---------------------------------------------------------------------------
extern "C" void kernel_launch(void* const* d_in, const int* in_sizes, int n_in,
                              void* d_out, int out_size)
{
    const float* X  = (const float*)d_in[0];
    const float* E  = (const float*)d_in[1];
    const float* wq = (const float*)d_in[2];
    const float* wk = (const float*)d_in[3];
    const float* wv = (const float*)d_in[4];
    const float* wo = (const float*)d_in[5];
    const float* bo = (const float*)d_in[6];
    float* out = (float*)d_out;

    float *pS, *pMqF, *pMoF;
    __half *pXf, *pEf, *pWqT, *pWkT, *pWvT, *pWoS, *pMqh, *pMoh, *pA, *pB2, *pP;
    cudaGetSymbolAddress((void**)&pS,   g_S);
    cudaGetSymbolAddress((void**)&pMqF, g_MqF);
    cudaGetSymbolAddress((void**)&pMoF, g_MoF);
    cudaGetSymbolAddress((void**)&pXf,  g_Xf);
    cudaGetSymbolAddress((void**)&pEf,  g_Ef);
    cudaGetSymbolAddress((void**)&pWqT, g_wqT);
    cudaGetSymbolAddress((void**)&pWkT, g_wkT);
    cudaGetSymbolAddress((void**)&pWvT, g_wvT);
    cudaGetSymbolAddress((void**)&pWoS, g_woS);
    cudaGetSymbolAddress((void**)&pMqh, g_Mqh);
    cudaGetSymbolAddress((void**)&pMoh, g_Moh);
    cudaGetSymbolAddress((void**)&pA,   g_A);
    cudaGetSymbolAddress((void**)&pB2,  g_B2);
    cudaGetSymbolAddress((void**)&pP,   g_P);

    cudaFuncSetAttribute(mma_gemm, cudaFuncAttributeMaxDynamicSharedMemorySize,
                         MM_SMEM);
    cudaFuncSetAttribute(mma_gemm_fa, cudaFuncAttributeMaxDynamicSharedMemorySize,
                         MM_SMEM);
    cudaFuncSetAttribute(mma_gemm_fb, cudaFuncAttributeMaxDynamicSharedMemorySize,
                         MM_SMEM);

    const float scale = 0.07905694150420949f;   // 160^-0.5

    // fp32 -> fp16 conversions
    cvt_h4<<<1024, 256>>>((const float4*)E, (__half2*)pEf,
                          (long)ROWS_KV * CDIM / 4, 1.f);
    cvt_h4<<<8192, 256>>>((const float4*)X, (__half2*)pXf,
                          (long)BATCH * SEQ * DIM / 4, 1.f);

    // weight prep
    transpose_pad<<<dim3(DIM / 32, EPAD / 32, HEADS), 256>>>(wq, pWqT, DIM);
    transpose_pad<<<dim3(CDIM / 32, EPAD / 32, HEADS), 256>>>(wk, pWkT, CDIM);
    transpose_pad<<<dim3(CDIM / 32, EPAD / 32, HEADS), 256>>>(wv, pWvT, CDIM);
    woslice<<<1024, 256>>>(wo, pWoS);

    // Mq[h][c][f] = sum_e wq[he][c] * wk[he][f]
    mma_gemm<<<dim3(CDIM / 128, DIM / 128, HEADS), 256, MM_SMEM>>>(
        pWqT, pWkT, pMqF, nullptr, EPAD, CDIM,
        (long)DIM * EPAD, (long)CDIM * EPAD, (long)DIM * CDIM);
    // Mo[h][e2][f] = sum_e wo[e2][he] * wv[he][f]
    mma_gemm<<<dim3(CDIM / 128, DIM / 128, HEADS), 256, MM_SMEM>>>(
        pWoS, pWvT, pMoF, nullptr, EPAD, CDIM,
        (long)DIM * EPAD, (long)CDIM * EPAD, (long)DIM * CDIM);

    cvt_h4<<<2048, 256>>>((const float4*)pMqF, (__half2*)pMqh,
                          (long)HEADS * DIM * CDIM / 4, scale);
    cvt_h4<<<2048, 256>>>((const float4*)pMoF, (__half2*)pMoh,
                          (long)HEADS * DIM * CDIM / 4, 1.f);

    // zero pads (Ef pad rows before fa/fb GEMMs read them)
    zero_pads<<<2048, 256>>>(pA, pB2, pEf);

    // Afold: E x Mq_h -> g_A   (row remap)
    mma_gemm_fa<<<dim3(DIM / 128, ROWS_KV_PAD / 128, HEADS), 256, MM_SMEM>>>(
        pEf, pMqh, pA);

    // B2: Mo_h x E -> g_B2     (column remap)
    mma_gemm_fb<<<dim3(ROWS_KV_PAD / 128, DIM / 128, HEADS), 256, MM_SMEM>>>(
        pMoh, pEf, pB2);

    // scores: S[b][s][j] = sum_c X[s][c] * AfoldT[j][c]
    mma_gemm<<<dim3(JPAD / 128, SEQ / 128, BATCH), 256, MM_SMEM>>>(
        pXf, pA, pS, nullptr, DIM, JPAD,
        (long)SEQ * DIM, (long)JPAD * DIM, (long)SEQ * JPAD);

    // fused softmax -> fp16 probs
    softmax77h<<<BATCH * SEQ, 256>>>(pS, pP);

    // output: out[b][s][e] = sum_j P[s][j] * B2T[e][j] + bias[e]
    mma_gemm<<<dim3(DIM / 128, SEQ / 128, BATCH), 256, MM_SMEM>>>(
        pP, pB2, out, bo, JPAD, DIM,
        (long)SEQ * JPAD, (long)DIM * JPAD, (long)SEQ * DIM);
}